// round 17
// baseline (speedup 1.0000x reference)
#include <cuda_runtime.h>
#include <cstddef>

// CTC batch cost, prob-domain forward with exact power-of-two renormalization.
// 512 CTAs x 64 threads. Warp 0 = R5's proven consumer: lane l owns lattice
// states 4l..4l+3 (lane 31 also 128); streams rows into an 8-slot cp.async
// ring (DIST=7) and runs the recurrence. Warp 1 = L2 warmer with REAL memory-
// level parallelism: 8 independent __ldcg uint4 loads per chunk into distinct
// registers (folded into a live XOR accumulator so none can be narrowed or
// dead-coded), free-running up to LEAD chunks ahead of consumption (volatile
// smem progress counter; no barriers -> no deadlock). The warmer drags lines
// DRAM->L2 with ~4KB in flight per warp, decoupling DRAM request generation
// from the consumer ring's latency feedback; the consumer's cp.async fills
// then complete at L2-hit latency. B=512, T=512, C=128, L=64, S=129.

#define CTC_B 512
#define CTC_T 512
#define CTC_C 128
#define CTC_L 64
#define CHUNK 8                    // steps per chunk == renorm period
#define NCHUNK (CTC_T / CHUNK)     // 64
#define DIST 7                     // cp.async chunk-groups kept in flight
#define SLOTS 8                    // ring slots (DIST+1 decouples refill/consume)
#define LEAD 16                    // warmer lead bound, in chunks (64 KB window)

__global__ __launch_bounds__(64)
void ctc_warp_kernel(const int* __restrict__ y_true,
                     const float* __restrict__ y_pred,
                     float* __restrict__ out)
{
    __shared__ float ring[SLOTS * CHUNK * CTC_C];   // 32 KB
    __shared__ volatile int prog;                   // chunks consumed so far

    const int b    = blockIdx.x;
    const int tid  = threadIdx.x;
    const int lane = tid & 31;
    const int wid  = tid >> 5;            // 0 = consumer, 1 = L2 warmer
    const unsigned FULL = 0xffffffffu;
    const float EPSF = 1e-7f;

    const float* row0 = y_pred + (size_t)b * CTC_T * CTC_C;

    if (tid == 0) prog = 0;
    __syncthreads();

    if (wid == 1) {
        // ───────── L2 warmer: 8 independent v4 loads per chunk ─────────
        // Each __ldcg covers 32 lanes x 16B = 512B; 8 of them (distinct
        // registers, no cross-dependencies) cover one 4KB chunk with MLP=8.
        // XOR-fold keeps every component live; sink at the end.
        unsigned acc = 0;
        for (int c = DIST; c < NCHUNK; ++c) {
            while (c > prog + LEAD) __nanosleep(64);
            const uint4* src = reinterpret_cast<const uint4*>(
                                   row0 + (size_t)c * CHUNK * CTC_C) + lane;
            const uint4 v0 = __ldcg(src + 0 * 32);
            const uint4 v1 = __ldcg(src + 1 * 32);
            const uint4 v2 = __ldcg(src + 2 * 32);
            const uint4 v3 = __ldcg(src + 3 * 32);
            const uint4 v4 = __ldcg(src + 4 * 32);
            const uint4 v5 = __ldcg(src + 5 * 32);
            const uint4 v6 = __ldcg(src + 6 * 32);
            const uint4 v7 = __ldcg(src + 7 * 32);
            acc ^= v0.x ^ v0.y ^ v0.z ^ v0.w;
            acc ^= v1.x ^ v1.y ^ v1.z ^ v1.w;
            acc ^= v2.x ^ v2.y ^ v2.z ^ v2.w;
            acc ^= v3.x ^ v3.y ^ v3.z ^ v3.w;
            acc ^= v4.x ^ v4.y ^ v4.z ^ v4.w;
            acc ^= v5.x ^ v5.y ^ v5.z ^ v5.w;
            acc ^= v6.x ^ v6.y ^ v6.z ^ v6.w;
            acc ^= v7.x ^ v7.y ^ v7.z ^ v7.w;
        }
        asm volatile("" :: "r"(acc));   // keep the loads live
        return;
    }

    // ───────── Consumer: R5 body, unchanged ─────────
    // Labels owned by this lane: k0 = 2*lane -> state 4l+1, k1 = 2*lane+1 -> state 4l+3
    const int c0 = y_true[b * CTC_L + 2 * lane];
    const int c1 = y_true[b * CTC_L + 2 * lane + 1];
    const int c1_prev = __shfl_up_sync(FULL, c1, 1);   // y[2l-1] lives in prev lane
    const bool skip1 = (lane > 0) && (c0 != c1_prev);  // state 4l+1: y[2l] != y[2l-1]
    const bool skip3 = (c1 != c0);                     // state 4l+3: y[2l+1] != y[2l]

    // cp.async one full row (512B) coalesced: lane takes 16B at offset lane*16.
    const unsigned ring_base = (unsigned)__cvta_generic_to_shared(ring);
    auto load_chunk = [&](int c) {   // rows c*CHUNK.. into ring slot c%SLOTS
        const int sbase = (c % SLOTS) * CHUNK;
        if (c < NCHUNK) {
            #pragma unroll
            for (int j = 0; j < CHUNK; ++j) {
                const int t = c * CHUNK + j;
                unsigned dst = ring_base + (unsigned)(((sbase + j) * CTC_C + lane * 4) * 4);
                const float* src = row0 + (size_t)t * CTC_C + lane * 4;
                asm volatile("cp.async.cg.shared.global [%0], [%1], 16;\n"
                             :: "r"(dst), "l"(src));
            }
        }
        asm volatile("cp.async.commit_group;\n" ::: "memory");  // commit even if empty
    };

    // Prologue: DIST chunk-groups in flight.
    for (int c = 0; c < DIST; ++c) load_chunk(c);

    // Virtual alpha_{-1} = (2^100, 0, 0, ...) at lane 0; true alpha = stored * 2^K.
    const float TWO100 = __int_as_float((100 + 127) << 23);  // 2^100
    float a0 = (lane == 0) ? TWO100 : 0.0f;
    float a1 = 0.0f, a2 = 0.0f, a3 = 0.0f, a4 = 0.0f;
    float pm1 = 0.0f;     // alpha_{t-1}[4l-1] (prev lane's a3), pipelined shfl
    int   K   = -100;     // integer log2 of the accumulated scale

    for (int c = 0; c < NCHUNK; ++c) {
        // Issue group c+DIST first (writes the slot consumed at iteration c-1,
        // whose LDS reads completed a full iteration ago) — keeps DIST groups
        // in flight through the compute phase.
        load_chunk(c + DIST);

        // Group c must be complete; up to DIST newer groups stay pending.
        asm volatile("cp.async.wait_group %0;\n" :: "n"(DIST) : "memory");
        __syncwarp();   // cross-lane visibility of cp.async-written smem

        // Publish consumption progress for the warmer warp.
        if (lane == 0) prog = c + 1;

        const int sbase = (c % SLOTS) * CHUNK;
        #pragma unroll
        for (int j = 0; j < CHUNK; ++j) {
            const float* rs = ring + (sbase + j) * CTC_C;
            const float pb = rs[CTC_C - 1] + EPSF;  // broadcast LDS
            const float p0 = rs[c0] + EPSF;         // scattered LDS
            const float p1 = rs[c1] + EPSF;

            // new[s] = p[s] * (a[s] + a[s-1] + skip*a[s-2]); states 4l..4l+3 (+128)
            const float n3 = p1 * ((a2 + (skip3 ? a1 : 0.0f)) + a3);   // s=4l+3 (label k1)
            const float n2 = pb * (a1 + a2);                           // s=4l+2 (blank)
            const float sh = __shfl_up_sync(FULL, n3, 1);              // next step's alpha[4l-1]
            const float n0 = pb * (a0 + pm1);                          // s=4l   (blank)
            const float n1 = p0 * ((a0 + (skip1 ? pm1 : 0.0f)) + a1);  // s=4l+1 (label k0)
            const float n4 = (lane == 31) ? pb * (a3 + a4) : 0.0f;     // s=128  (last blank)

            pm1 = (lane == 0) ? 0.0f : sh;
            a0 = n0; a1 = n1; a2 = n2; a3 = n3; a4 = n4;
        }

        // Exact renorm: warp max via redux (bits order-preserving for non-negative
        // floats), round down to 2^k, rescale so max sits in [2^100, 2^101).
        // Scale 2^(100-k) applied as two exact power-of-2 multiplies; K accumulates
        // the exact integer log2 of the total scale (zero rounding added).
        float m = fmaxf(fmaxf(fmaxf(a0, a1), fmaxf(a2, a3)), a4);
        m = __uint_as_float(__reduce_max_sync(FULL, __float_as_uint(m)));
        const int k = (int)((__float_as_uint(m) >> 23) & 0xff) - 127;  // floor(log2 m)
        K += k - 100;
        const float s1 = __int_as_float((127 - k) << 23);  // 2^-k   (exact)
        a0 = a0 * s1 * TWO100;
        a1 = a1 * s1 * TWO100;
        a2 = a2 * s1 * TWO100;
        a3 = a3 * s1 * TWO100;
        a4 = a4 * s1 * TWO100;
        pm1 = pm1 * s1 * TWO100;
    }

    // ll = log(alpha_T[S-2] + alpha_T[S-1]) + K*ln2 ; states 127,128 live in lane 31.
    if (lane == 31) {
        out[b] = -(logf(a3 + a4) + (float)K * 0.693147180559945309f);
    }
}

extern "C" void kernel_launch(void* const* d_in, const int* in_sizes, int n_in,
                              void* d_out, int out_size)
{
    // Resolve inputs by size (y_true: 512*64 int32, y_pred: 512*512*128 float32).
    const void* p0 = d_in[0];
    const void* p1 = d_in[1];
    const int* y_true;
    const float* y_pred;
    if (in_sizes[0] == CTC_B * CTC_L) {
        y_true = (const int*)p0;
        y_pred = (const float*)p1;
    } else {
        y_true = (const int*)p1;
        y_pred = (const float*)p0;
    }
    float* out = (float*)d_out;

    ctc_warp_kernel<<<CTC_B, 64>>>(y_true, y_pred, out);
}